// round 5
// baseline (speedup 1.0000x reference)
#include <cuda_runtime.h>

#define NXg 1024
#define NYg 85
#define N_AMPS 1500
#define NCH 375          // N_AMPS / 4 chunks
#define WCHUNKS 7        // warp-uniform window: 7 float4 chunks = 28 amps >= 23 needed

__device__ __forceinline__ float ex2f(float x) {
    float r;
    asm("ex2.approx.ftz.f32 %0, %1;" : "=f"(r) : "f"(x));
    return r;
}

__global__ __launch_bounds__(96)
void echellogram_kernel(
    const int*   __restrict__ index_p,
    const float* __restrict__ bkg_p,
    const float* __restrict__ s_coeffs,
    const float* __restrict__ amps,
    const float* __restrict__ smooth_p,
    const float* __restrict__ lam_coeffs,
    const float* __restrict__ p_coeffs,
    const float* __restrict__ src_amps,
    const float* __restrict__ fiducial,
    const float* __restrict__ lam_vector,
    float*       __restrict__ out)
{
    const float SIGMA        = 0.42f;
    const float INV_SIGMA    = 1.0f / 0.42f;
    const float SLIT         = 12.0f;
    const float INV_SQRT_2PI = 0.3989422804014327f;
    const float LOG_SQRT_2PI = 0.9189385332046727f;
    const float LOG2E        = 1.4426950408889634f;

    int x = blockIdx.x;
    int y_real = threadIdx.x;
    int y = min(y_real, NYg - 1);       // keep full warps active (no divergence)
    float xf = (float)x;
    float yf = (float)y;

    // --- scalar params; dependent chain (index -> p_coeffs) issued first ---
    int   idx        = index_p[0];
    float lam0_v     = lam_vector[0];
    float lamN_v     = lam_vector[N_AMPS - 1];
    float bkg        = bkg_p[0];
    float smoothness = smooth_p[0];
    float s0 = s_coeffs[0], s1 = s_coeffs[1], s2 = s_coeffs[2];
    float c0 = lam_coeffs[0], c1 = lam_coeffs[1], c2 = lam_coeffs[2], c3 = lam_coeffs[3];
    float f0 = fiducial[0],   f1 = fiducial[1];
    float pc0 = p_coeffs[2 * idx + 0];
    float pc1 = p_coeffs[2 * idx + 1];

    // --- along-slit coordinate & wavelength surface (ref op order) ---
    float ss = s1 * (yf - s0 - s2 * xf);

    float xn = (xf - 512.0f) / 512.0f;
    float yn = (yf - 42.5f) / 42.5f;
    float cx1 = f1 * (1.0f + c1 * 0.01f) * 512.0f;
    float cx2 = 1.0f + c2;
    float lam = f0 + c0 + cx1 * xn + cx2 * (2.0f * xn * xn - 1.0f) + c3 * yn;

    // --- per-lane needed window, then warp-uniform union ---
    float dlam = (lamN_v - lam0_v) * (1.0f / (float)(N_AMPS - 1));
    int lo_c, hi_c;
    if (fabsf(dlam) > 1e-20f) {
        float inv_dlam = 1.0f / dlam;
        float tc = (lam - lam0_v) * inv_dlam;
        float hw = 5.0f * SIGMA * fabsf(inv_dlam);   // 5-sigma half-window
        int lo = max(0,          (int)floorf(tc - hw));
        int hi = min(N_AMPS - 1, (int)ceilf (tc + hw));
        lo_c = lo >> 2;
        hi_c = hi >> 2;
    } else {
        lo_c = 0; hi_c = NCH - 1;                    // degenerate: sum everything
    }
    int k0 = (int)__reduce_min_sync(0xffffffffu, (unsigned)lo_c);
    int k1 = (int)__reduce_max_sync(0xffffffffu, (unsigned)hi_c);
    k0 = min(k0, NCH - WCHUNKS);                     // fixed part stays in bounds

    const float4* __restrict__ lam4 = (const float4*)lam_vector;
    const float4* __restrict__ amp4 = (const float4*)amps;
    const float4* __restrict__ srv4 = (const float4*)src_amps;

    const float A = 0.5f * LOG2E * INV_SIGMA * INV_SIGMA;   // p = 2^(-A d^2)

    float sky0 = 0.0f, sky1 = 0.0f, src0 = 0.0f, src1 = 0.0f;
    #pragma unroll
    for (int k = 0; k < WCHUNKS; ++k) {
        int a = k0 + k;                 // warp-uniform -> broadcast LDG.128
        float4 lv = lam4[a];
        float4 av = amp4[a];
        float4 sv = srv4[a];
        float d0 = lam - lv.x;
        float d1 = lam - lv.y;
        float d2 = lam - lv.z;
        float d3 = lam - lv.w;
        float p0 = ex2f(-A * d0 * d0);
        float p1 = ex2f(-A * d1 * d1);
        float p2 = ex2f(-A * d2 * d2);
        float p3 = ex2f(-A * d3 * d3);
        sky0 = fmaf(av.x, p0, sky0);
        sky1 = fmaf(av.y, p1, sky1);
        sky0 = fmaf(av.z, p2, sky0);
        sky1 = fmaf(av.w, p3, sky1);
        src0 = fmaf(sv.x, p0, src0);
        src1 = fmaf(sv.y, p1, src1);
        src0 = fmaf(sv.z, p2, src0);
        src1 = fmaf(sv.w, p3, src1);
    }
    // generic tail (not taken for the benchmark's parameters)
    for (int a = k0 + WCHUNKS; a <= k1; ++a) {
        float4 lv = lam4[a];
        float4 av = amp4[a];
        float4 sv = srv4[a];
        float d0 = lam - lv.x, d1 = lam - lv.y, d2 = lam - lv.z, d3 = lam - lv.w;
        float p0 = ex2f(-A * d0 * d0);
        float p1 = ex2f(-A * d1 * d1);
        float p2 = ex2f(-A * d2 * d2);
        float p3 = ex2f(-A * d3 * d3);
        sky0 = fmaf(av.x, p0, sky0);
        sky1 = fmaf(av.y, p1, sky1);
        sky0 = fmaf(av.z, p2, sky0);
        sky1 = fmaf(av.w, p3, sky1);
        src0 = fmaf(sv.x, p0, src0);
        src1 = fmaf(sv.y, p1, src1);
        src0 = fmaf(sv.z, p2, src0);
        src1 = fmaf(sv.w, p3, src1);
    }

    float norm = INV_SQRT_2PI * INV_SIGMA;
    float sky = (sky0 + sky1) * norm;
    float src = (src0 + src1) * norm;

    // --- soft slit mask (sigmoids via ex2) ---
    float inv_beta = ex2f(-smoothness * LOG2E);
    float e1 = 1.0f / (1.0f + ex2f(-(ss * inv_beta) * LOG2E));
    float e2 = 1.0f / (1.0f + ex2f(-((SLIT - ss) * inv_beta) * LOG2E));
    float emask = e1 * e2;

    // --- source spatial profile ---
    float sig_s = ex2f(pc1 * LOG2E);
    float u = (ss - pc0) / sig_s;
    float src_prof = ex2f(fmaf(-0.5f * u, u, -pc1 - LOG_SQRT_2PI) * LOG2E);

    if (y_real < NYg)
        out[x * NYg + y_real] = emask * sky + src_prof * src + bkg;
}

extern "C" void kernel_launch(void* const* d_in, const int* in_sizes, int n_in,
                              void* d_out, int out_size) {
    (void)in_sizes; (void)n_in; (void)out_size;
    const int*   index_p    = (const int*)  d_in[0];
    const float* bkg_p      = (const float*)d_in[1];
    const float* s_coeffs   = (const float*)d_in[2];
    const float* amps       = (const float*)d_in[3];
    const float* smooth_p   = (const float*)d_in[4];
    const float* lam_coeffs = (const float*)d_in[5];
    const float* p_coeffs   = (const float*)d_in[6];
    const float* src_amps   = (const float*)d_in[7];
    const float* fiducial   = (const float*)d_in[8];
    const float* lam_vector = (const float*)d_in[9];
    float* out = (float*)d_out;

    echellogram_kernel<<<NXg, 96>>>(
        index_p, bkg_p, s_coeffs, amps, smooth_p, lam_coeffs,
        p_coeffs, src_amps, fiducial, lam_vector, out);
}